// round 3
// baseline (speedup 1.0000x reference)
#include <cuda_runtime.h>

#define H     128
#define IN_D  8
#define TT    512
#define OUTD  4
#define FCH   64
#define MB    32
#define NTHR  512

typedef unsigned long long u64;

// transposed weights + folded constants
__device__ float g_WT0ih[IN_D * 512];
__device__ float g_WT0hh[H * 512];
__device__ float g_WT1ih[H * 512];
__device__ float g_WT1hh[H * 512];
__device__ float g_W1T[H * FCH];
__device__ float g_b0[512];
__device__ float g_b1[512];
__device__ float g_bnsc[H];
__device__ float g_bnsh[H];

__global__ void prep_kernel(const float* __restrict__ Wih0, const float* __restrict__ Whh0,
                            const float* __restrict__ bih0, const float* __restrict__ bhh0,
                            const float* __restrict__ Wih1, const float* __restrict__ Whh1,
                            const float* __restrict__ bih1, const float* __restrict__ bhh1,
                            const float* __restrict__ gam,  const float* __restrict__ bet,
                            const float* __restrict__ mean, const float* __restrict__ var,
                            const float* __restrict__ W1)
{
    int i = blockIdx.x * blockDim.x + threadIdx.x;
    int st = gridDim.x * blockDim.x;
    for (int idx = i; idx < IN_D * 512; idx += st) {
        int k = idx / 512, j = idx % 512;
        g_WT0ih[idx] = Wih0[j * IN_D + k];
    }
    for (int idx = i; idx < H * 512; idx += st) {
        int k = idx / 512, j = idx % 512;
        g_WT0hh[idx] = Whh0[j * H + k];
        g_WT1ih[idx] = Wih1[j * H + k];
        g_WT1hh[idx] = Whh1[j * H + k];
    }
    for (int idx = i; idx < 512; idx += st) {
        g_b0[idx] = bih0[idx] + bhh0[idx];
        g_b1[idx] = bih1[idx] + bhh1[idx];
    }
    for (int idx = i; idx < H * FCH; idx += st) {
        int k = idx / FCH, j = idx % FCH;
        g_W1T[idx] = W1[j * H + k];
    }
    for (int idx = i; idx < H; idx += st) {
        float s = gam[idx] * rsqrtf(var[idx] + 1e-5f);
        g_bnsc[idx] = s;
        g_bnsh[idx] = bet[idx] - mean[idx] * s;
    }
}

__device__ __forceinline__ u64 splat2(float x) {
    u64 r; unsigned xi = __float_as_uint(x);
    asm("mov.b64 %0, {%1, %1};" : "=l"(r) : "r"(xi));
    return r;
}
__device__ __forceinline__ void fma2(u64& d, u64 a, u64 b) {
    asm("fma.rn.f32x2 %0, %1, %2, %0;" : "+l"(d) : "l"(a), "l"(b));
}
__device__ __forceinline__ float2 unpk(u64 v) {
    unsigned lo, hi;
    asm("mov.b64 {%0, %1}, %2;" : "=r"(lo), "=r"(hi) : "l"(v));
    return make_float2(__uint_as_float(lo), __uint_as_float(hi));
}
__device__ __forceinline__ float sigm(float v)  { return __fdividef(1.f, 1.f + __expf(-v)); }
__device__ __forceinline__ float tanhh(float v) { return 2.f * __fdividef(1.f, 1.f + __expf(-2.f * v)) - 1.f; }

// acc[g][mm] : packed over j-pair (j0, j0+1), mm = row m0+mm
// acc[g][mm] += splat(a[k][m0+mm]) * W[k][g*128 + j0 .. j0+1]
__device__ __forceinline__ void accum(u64 (&acc)[4][4],
                                      const float* __restrict__ WT,
                                      const float* __restrict__ aT,
                                      int K, int m0, int j0)
{
    const float* wp = WT + j0;
    const float* ap = aT + m0;
#pragma unroll 2
    for (int k = 0; k < K; k++) {
        float4 a = *reinterpret_cast<const float4*>(ap);
        u64 w0 = *reinterpret_cast<const u64*>(wp);
        u64 w1 = *reinterpret_cast<const u64*>(wp + H);
        u64 w2 = *reinterpret_cast<const u64*>(wp + 2 * H);
        u64 w3 = *reinterpret_cast<const u64*>(wp + 3 * H);
        u64 s0 = splat2(a.x), s1 = splat2(a.y), s2 = splat2(a.z), s3 = splat2(a.w);
        fma2(acc[0][0], s0, w0); fma2(acc[0][1], s1, w0);
        fma2(acc[0][2], s2, w0); fma2(acc[0][3], s3, w0);
        fma2(acc[1][0], s0, w1); fma2(acc[1][1], s1, w1);
        fma2(acc[1][2], s2, w1); fma2(acc[1][3], s3, w1);
        fma2(acc[2][0], s0, w2); fma2(acc[2][1], s1, w2);
        fma2(acc[2][2], s2, w2); fma2(acc[2][3], s3, w2);
        fma2(acc[3][0], s0, w3); fma2(acc[3][1], s1, w3);
        fma2(acc[3][2], s2, w3); fma2(acc[3][3], s3, w3);
        wp += 512; ap += MB;
    }
}

// gates + state update; writes h (transposed [j][m]) to shHw; optional BN -> shHN
__device__ __forceinline__ void cell_epi(u64 (&acc)[4][4], float* cst,
                                         float* __restrict__ shHw, int m0, int j0,
                                         float* __restrict__ shHN,
                                         float2 bns, float2 bnh, bool dec)
{
#pragma unroll
    for (int mm = 0; mm < 4; mm++) {
        float2 zi = unpk(acc[0][mm]);
        float2 zf = unpk(acc[1][mm]);
        float2 zg = unpk(acc[2][mm]);
        float2 zo = unpk(acc[3][mm]);
        int m = m0 + mm;
        {   // lane j0
            float c = sigm(zf.x) * cst[mm * 2] + sigm(zi.x) * tanhh(zg.x);
            cst[mm * 2] = c;
            float h = sigm(zo.x) * tanhh(c);
            shHw[j0 * MB + m] = h;
            if (dec) shHN[j0 * MB + m] = h * bns.x + bnh.x;
        }
        {   // lane j0+1
            float c = sigm(zf.y) * cst[mm * 2 + 1] + sigm(zi.y) * tanhh(zg.y);
            cst[mm * 2 + 1] = c;
            float h = sigm(zo.y) * tanhh(c);
            shHw[(j0 + 1) * MB + m] = h;
            if (dec) shHN[(j0 + 1) * MB + m] = h * bns.y + bnh.y;
        }
    }
}

// smem layout (floats): double-buffered h0/h1
#define SM_X    0
#define SM_H0A  (SM_X   + IN_D * MB)
#define SM_H0B  (SM_H0A + H * MB)
#define SM_H1A  (SM_H0B + H * MB)
#define SM_H1B  (SM_H1A + H * MB)
#define SM_HN   (SM_H1B + H * MB)
#define SM_W1   (SM_HN  + H * MB)
#define SM_O1   (SM_W1  + H * FCH)
#define SM_O2   (SM_O1  + MB * FCH)
#define SM_BN   (SM_O2  + MB * OUTD)
#define SM_TOT  (SM_BN  + 2 * H)

__global__ void __launch_bounds__(NTHR, 1)
lstm_main(const float* __restrict__ x,
          const float* __restrict__ W2, const float* __restrict__ b2,
          const float* __restrict__ Wf, const float* __restrict__ bf,
          const float* __restrict__ b1fc,
          float* __restrict__ out, int steps)
{
    extern __shared__ float sm[];
    float* shX  = sm + SM_X;
    float* shHN = sm + SM_HN;
    float* shW1 = sm + SM_W1;
    float* shO1 = sm + SM_O1;
    float* shO2 = sm + SM_O2;
    float* shBN = sm + SM_BN;

    const int tid = threadIdx.x;
    const int j0  = (tid & 63) * 2;      // j-pair
    const int m0  = (tid >> 6) * 4;      // 4 rows
    const int b0  = blockIdx.x * MB;

    // init
    for (int i = tid; i < 4 * H * MB; i += NTHR) sm[SM_H0A + i] = 0.f;
    for (int i = tid; i < H * FCH; i += NTHR) shW1[i] = g_W1T[i];
    if (tid < H) { shBN[tid] = g_bnsc[tid]; shBN[H + tid] = g_bnsh[tid]; }

    float c0r[8], c1r[8];
#pragma unroll
    for (int i = 0; i < 8; i++) { c0r[i] = 0.f; c1r[i] = 0.f; }

    u64 b0p[4], b1p[4];
#pragma unroll
    for (int g = 0; g < 4; g++) {
        b0p[g] = *reinterpret_cast<const u64*>(g_b0 + g * H + j0);
        b1p[g] = *reinterpret_cast<const u64*>(g_b1 + g * H + j0);
    }

    // stage x[0]
    if (tid < IN_D * MB) {
        int m = tid >> 3, ii = tid & 7;
        shX[ii * MB + m] = x[((size_t)(b0 + m) * TT + 0) * IN_D + ii];
    }
    __syncthreads();

    float2 bns = *reinterpret_cast<const float2*>(shBN + j0);
    float2 bnh = *reinterpret_cast<const float2*>(shBN + H + j0);

    float* h0r = sm + SM_H0A; float* h0w = sm + SM_H0B;
    float* h1r = sm + SM_H1A; float* h1w = sm + SM_H1B;

    const int total = TT + steps;
    for (int t = 0; t < total; t++) {
        bool dec = (t >= TT);
        u64 acc[4][4];

        // ---- layer 0 ----
#pragma unroll
        for (int g = 0; g < 4; g++)
#pragma unroll
            for (int mm = 0; mm < 4; mm++) acc[g][mm] = b0p[g];
        accum(acc, g_WT0ih, shX, IN_D, m0, j0);
        accum(acc, g_WT0hh, h0r, H,    m0, j0);
        cell_epi(acc, c0r, h0w, m0, j0, shHN, bns, bnh, false);
        __syncthreads();                       // h0w visible (shX reads done)

        // ---- layer 1 ----
#pragma unroll
        for (int g = 0; g < 4; g++)
#pragma unroll
            for (int mm = 0; mm < 4; mm++) acc[g][mm] = b1p[g];
        accum(acc, g_WT1ih, h0w, H, m0, j0);
        accum(acc, g_WT1hh, h1r, H, m0, j0);

        // prefetch next encoder x while L1 accumulates (shX readers finished at sync above)
        if (t + 1 < TT && tid < IN_D * MB) {
            int m = tid >> 3, ii = tid & 7;
            shX[ii * MB + m] = x[((size_t)(b0 + m) * TT + (t + 1)) * IN_D + ii];
        }

        cell_epi(acc, c1r, h1w, m0, j0, shHN, bns, bnh, dec);
        __syncthreads();                       // h1w (+HN, shX) visible

        if (dec) {
            int d = t - TT;
            // FC1: relu(BN(h1) @ W1^T + b1) -> shO1[m][64]
#pragma unroll
            for (int i = 0; i < (MB * FCH) / NTHR; i++) {
                int idx = tid + i * NTHR;
                int m = idx >> 6, n = idx & 63;
                float s = b1fc[n];
#pragma unroll 8
                for (int k = 0; k < H; k++) s += shHN[k * MB + m] * shW1[k * FCH + n];
                shO1[idx] = fmaxf(s, 0.f);
            }
            __syncthreads();
            // FC2 + output write
            if (tid < MB * OUTD) {
                int m = tid >> 2, o = tid & 3;
                float s = b2[o];
#pragma unroll 8
                for (int k = 0; k < FCH; k++) s += shO1[m * FCH + k] * W2[o * FCH + k];
                shO2[tid] = s;
                out[((size_t)(b0 + m) * steps + d) * OUTD + o] = s;
            }
            __syncthreads();
            // feedback: xin = out @ Wf^T + bf -> shX (transposed)
            if (tid < IN_D * MB) {
                int m = tid >> 3, i = tid & 7;
                float s = bf[i];
#pragma unroll
                for (int o = 0; o < OUTD; o++) s += shO2[m * OUTD + o] * Wf[i * OUTD + o];
                shX[i * MB + m] = s;
            }
            __syncthreads();
        }

        // swap double buffers
        float* tmp;
        tmp = h0r; h0r = h0w; h0w = tmp;
        tmp = h1r; h1r = h1w; h1w = tmp;
    }
}

extern "C" void kernel_launch(void* const* d_in, const int* in_sizes, int n_in,
                              void* d_out, int out_size) {
    const float* x    = (const float*)d_in[0];
    const float* Wih0 = (const float*)d_in[1];
    const float* Whh0 = (const float*)d_in[2];
    const float* bih0 = (const float*)d_in[3];
    const float* bhh0 = (const float*)d_in[4];
    const float* Wih1 = (const float*)d_in[5];
    const float* Whh1 = (const float*)d_in[6];
    const float* bih1 = (const float*)d_in[7];
    const float* bhh1 = (const float*)d_in[8];
    const float* gam  = (const float*)d_in[9];
    const float* bet  = (const float*)d_in[10];
    const float* mean = (const float*)d_in[11];
    const float* var  = (const float*)d_in[12];
    const float* W1   = (const float*)d_in[13];
    const float* b1   = (const float*)d_in[14];
    const float* W2   = (const float*)d_in[15];
    const float* b2   = (const float*)d_in[16];
    const float* Wf   = (const float*)d_in[17];
    const float* bf   = (const float*)d_in[18];
    float* out = (float*)d_out;

    int B = in_sizes[0] / (TT * IN_D);
    int steps = out_size / (B * OUTD);

    cudaFuncSetAttribute(lstm_main, cudaFuncAttributeMaxDynamicSharedMemorySize,
                         SM_TOT * sizeof(float));

    prep_kernel<<<256, 256>>>(Wih0, Whh0, bih0, bhh0, Wih1, Whh1, bih1, bhh1,
                              gam, bet, mean, var, W1);
    lstm_main<<<B / MB, NTHR, SM_TOT * sizeof(float)>>>(x, W2, b2, Wf, bf, b1, out, steps);
}

// round 4
// speedup vs baseline: 1.3600x; 1.3600x over previous
#include <cuda_runtime.h>

#define H     128
#define IN_D  8
#define TT    512
#define OUTD  4
#define FCH   64
#define MB    32
#define NTHR  512
#define KT    8                 // k-rows per tile
#define TILE_F (KT * 512)       // 4096 floats = 16KB
#define NSLOT 4                 // ring slots
#define TPS   49                // tiles per step: 1 (Wih0) + 16 (Whh0) + 16 (Wih1) + 16 (Whh1)

typedef unsigned long long u64;

// transposed weights [k][512] + folded constants
__device__ __align__(16) float g_WT0ih[IN_D * 512];
__device__ __align__(16) float g_WT0hh[H * 512];
__device__ __align__(16) float g_WT1ih[H * 512];
__device__ __align__(16) float g_WT1hh[H * 512];
__device__ __align__(16) float g_W1T[H * FCH];
__device__ float g_b0[512];
__device__ float g_b1[512];
__device__ float g_bnsc[H];
__device__ float g_bnsh[H];

__global__ void prep_kernel(const float* __restrict__ Wih0, const float* __restrict__ Whh0,
                            const float* __restrict__ bih0, const float* __restrict__ bhh0,
                            const float* __restrict__ Wih1, const float* __restrict__ Whh1,
                            const float* __restrict__ bih1, const float* __restrict__ bhh1,
                            const float* __restrict__ gam,  const float* __restrict__ bet,
                            const float* __restrict__ mean, const float* __restrict__ var,
                            const float* __restrict__ W1)
{
    int i = blockIdx.x * blockDim.x + threadIdx.x;
    int st = gridDim.x * blockDim.x;
    for (int idx = i; idx < IN_D * 512; idx += st) {
        int k = idx / 512, j = idx % 512;
        g_WT0ih[idx] = Wih0[j * IN_D + k];
    }
    for (int idx = i; idx < H * 512; idx += st) {
        int k = idx / 512, j = idx % 512;
        g_WT0hh[idx] = Whh0[j * H + k];
        g_WT1ih[idx] = Wih1[j * H + k];
        g_WT1hh[idx] = Whh1[j * H + k];
    }
    for (int idx = i; idx < 512; idx += st) {
        g_b0[idx] = bih0[idx] + bhh0[idx];
        g_b1[idx] = bih1[idx] + bhh1[idx];
    }
    for (int idx = i; idx < H * FCH; idx += st) {
        int k = idx / FCH, j = idx % FCH;
        g_W1T[idx] = W1[j * H + k];
    }
    for (int idx = i; idx < H; idx += st) {
        float s = gam[idx] * rsqrtf(var[idx] + 1e-5f);
        g_bnsc[idx] = s;
        g_bnsh[idx] = bet[idx] - mean[idx] * s;
    }
}

__device__ __forceinline__ u64 splat2(float x) {
    u64 r; unsigned xi = __float_as_uint(x);
    asm("mov.b64 %0, {%1, %1};" : "=l"(r) : "r"(xi));
    return r;
}
__device__ __forceinline__ void fma2(u64& d, u64 a, u64 b) {
    asm("fma.rn.f32x2 %0, %1, %2, %0;" : "+l"(d) : "l"(a), "l"(b));
}
__device__ __forceinline__ float2 unpk(u64 v) {
    unsigned lo, hi;
    asm("mov.b64 {%0, %1}, %2;" : "=r"(lo), "=r"(hi) : "l"(v));
    return make_float2(__uint_as_float(lo), __uint_as_float(hi));
}
__device__ __forceinline__ float sigm(float v)  { return __fdividef(1.f, 1.f + __expf(-v)); }
__device__ __forceinline__ float tanhh(float v) { return 2.f * __fdividef(1.f, 1.f + __expf(-2.f * v)) - 1.f; }

__device__ __forceinline__ unsigned smem_u32(const void* p) {
    return (unsigned)__cvta_generic_to_shared(p);
}

// stage one 8-row weight tile (16KB) into ring slot via cp.async; 2 x 16B per thread
__device__ __forceinline__ void stage_tile(float* __restrict__ ring, int slot, int r, int tid) {
    const float* src;
    if (r == 0)       src = g_WT0ih;
    else if (r <= 16) src = g_WT0hh + (r - 1)  * TILE_F;
    else if (r <= 32) src = g_WT1ih + (r - 17) * TILE_F;
    else              src = g_WT1hh + (r - 33) * TILE_F;
    unsigned ds = smem_u32(ring + slot * TILE_F);
#pragma unroll
    for (int i = 0; i < 2; i++) {
        int c = tid + i * NTHR;
        asm volatile("cp.async.cg.shared.global [%0], [%1], 16;"
                     :: "r"(ds + c * 16), "l"(src + c * 4));
    }
}
#define CP_COMMIT() asm volatile("cp.async.commit_group;" ::: "memory")
#define CP_WAIT2()  asm volatile("cp.async.wait_group 2;"  ::: "memory")

// accumulate one 8-k tile: acc[g][mp] (m-pair packed) += a[k][m] * w[k][g*128+jg]
__device__ __forceinline__ void accum_tile(u64 (&acc)[4][4],
                                           const float* __restrict__ w,   // slot base + jg
                                           const float* __restrict__ aT,  // activation rows
                                           int m0)
{
#pragma unroll
    for (int k = 0; k < KT; k++) {
        float w0 = w[k * 512];
        float w1 = w[k * 512 + 128];
        float w2 = w[k * 512 + 256];
        float w3 = w[k * 512 + 384];
        ulonglong2 va = *reinterpret_cast<const ulonglong2*>(aT + k * MB + m0);
        ulonglong2 vb = *reinterpret_cast<const ulonglong2*>(aT + k * MB + m0 + 4);
        u64 s0 = splat2(w0), s1 = splat2(w1), s2 = splat2(w2), s3 = splat2(w3);
        fma2(acc[0][0], va.x, s0); fma2(acc[0][1], va.y, s0);
        fma2(acc[0][2], vb.x, s0); fma2(acc[0][3], vb.y, s0);
        fma2(acc[1][0], va.x, s1); fma2(acc[1][1], va.y, s1);
        fma2(acc[1][2], vb.x, s1); fma2(acc[1][3], vb.y, s1);
        fma2(acc[2][0], va.x, s2); fma2(acc[2][1], va.y, s2);
        fma2(acc[2][2], vb.x, s2); fma2(acc[2][3], vb.y, s2);
        fma2(acc[3][0], va.x, s3); fma2(acc[3][1], va.y, s3);
        fma2(acc[3][2], vb.x, s3); fma2(acc[3][3], vb.y, s3);
    }
}

// gates + state update for thread's (jg, m0..m0+7); h -> shHw, optional BN -> shHN
__device__ __forceinline__ void cell_epi(u64 (&acc)[4][4], float* cst,
                                         float* __restrict__ shHw, int m0, int jg,
                                         float* __restrict__ shHN,
                                         float bns, float bnh, bool dec)
{
#pragma unroll
    for (int mp = 0; mp < 4; mp++) {
        float2 zi = unpk(acc[0][mp]);
        float2 zf = unpk(acc[1][mp]);
        float2 zg = unpk(acc[2][mp]);
        float2 zo = unpk(acc[3][mp]);
        int m = m0 + mp * 2;
        {
            float c = sigm(zf.x) * cst[mp * 2] + sigm(zi.x) * tanhh(zg.x);
            cst[mp * 2] = c;
            float h = sigm(zo.x) * tanhh(c);
            shHw[jg * MB + m] = h;
            if (dec) shHN[jg * MB + m] = h * bns + bnh;
        }
        {
            float c = sigm(zf.y) * cst[mp * 2 + 1] + sigm(zi.y) * tanhh(zg.y);
            cst[mp * 2 + 1] = c;
            float h = sigm(zo.y) * tanhh(c);
            shHw[jg * MB + m + 1] = h;
            if (dec) shHN[jg * MB + m + 1] = h * bns + bnh;
        }
    }
}

// smem layout (floats)
#define SM_RING 0
#define SM_X    (SM_RING + NSLOT * TILE_F)
#define SM_H0A  (SM_X    + IN_D * MB)
#define SM_H0B  (SM_H0A  + H * MB)
#define SM_H1A  (SM_H0B  + H * MB)
#define SM_H1B  (SM_H1A  + H * MB)
#define SM_HN   (SM_H1B  + H * MB)
#define SM_W1   (SM_HN   + H * MB)
#define SM_O1   (SM_W1   + H * FCH)
#define SM_O2   (SM_O1   + MB * FCH)
#define SM_BN   (SM_O2   + MB * OUTD)
#define SM_TOT  (SM_BN   + 2 * H)

__global__ void __launch_bounds__(NTHR, 1)
lstm_main(const float* __restrict__ x,
          const float* __restrict__ W2, const float* __restrict__ b2,
          const float* __restrict__ Wf, const float* __restrict__ bf,
          const float* __restrict__ b1fc,
          float* __restrict__ out, int steps)
{
    extern __shared__ float sm[];
    float* ring = sm + SM_RING;
    float* shX  = sm + SM_X;
    float* shHN = sm + SM_HN;
    float* shW1 = sm + SM_W1;
    float* shO1 = sm + SM_O1;
    float* shO2 = sm + SM_O2;
    float* shBN = sm + SM_BN;

    const int tid = threadIdx.x;
    const int jg  = tid & 127;          // j within gate: 0..127
    const int m0  = (tid >> 7) * 8;     // 4 m-groups of 8 rows
    const int b0  = blockIdx.x * MB;

    for (int i = tid; i < 4 * H * MB; i += NTHR) sm[SM_H0A + i] = 0.f;
    for (int i = tid; i < H * FCH; i += NTHR) shW1[i] = g_W1T[i];
    if (tid < H) { shBN[tid] = g_bnsc[tid]; shBN[H + tid] = g_bnsh[tid]; }

    float c0r[8], c1r[8];
#pragma unroll
    for (int i = 0; i < 8; i++) { c0r[i] = 0.f; c1r[i] = 0.f; }

    u64 b0p[4], b1p[4];
#pragma unroll
    for (int g = 0; g < 4; g++) {
        b0p[g] = splat2(g_b0[g * H + jg]);
        b1p[g] = splat2(g_b1[g * H + jg]);
    }
    float bns = g_bnsc[jg], bnh = g_bnsh[jg];

    // stage x[0]
    if (tid < IN_D * MB) {
        int m = tid >> 3, ii = tid & 7;
        shX[ii * MB + m] = x[((size_t)(b0 + m) * TT + 0) * IN_D + ii];
    }
    __syncthreads();

    float* h0r = sm + SM_H0A; float* h0w = sm + SM_H0B;
    float* h1r = sm + SM_H1A; float* h1w = sm + SM_H1B;

    const int total = TT + steps;
    const int tiles_total = total * TPS;

    int p = 0, r = 0;          // producer tile counter and p % TPS
#pragma unroll
    for (int i = 0; i < 3; i++) {
        stage_tile(ring, p & (NSLOT - 1), r, tid);
        CP_COMMIT();
        p++; r++;
    }
    int cons = 0;              // consumer tile counter

    for (int t = 0; t < total; t++) {
        bool dec = (t >= TT);
        u64 acc[4][4];

        // ---- layer 0: tiles 0..16 ----
#pragma unroll
        for (int g = 0; g < 4; g++)
#pragma unroll
            for (int mp = 0; mp < 4; mp++) acc[g][mp] = b0p[g];
        for (int ta = 0; ta < 17; ta++) {
            CP_WAIT2();
            __syncthreads();
            if (p < tiles_total) stage_tile(ring, p & (NSLOT - 1), r, tid);
            CP_COMMIT();
            p++; r = (r == TPS - 1) ? 0 : r + 1;
            const float* wb  = ring + (cons & (NSLOT - 1)) * TILE_F + jg;
            const float* act = (ta == 0) ? shX : h0r + (ta - 1) * KT * MB;
            accum_tile(acc, wb, act, m0);
            cons++;
        }
        cell_epi(acc, c0r, h0w, m0, jg, shHN, bns, bnh, false);
        // h0w visibility: next tile's __syncthreads covers it

        // ---- layer 1: tiles 17..48 ----
#pragma unroll
        for (int g = 0; g < 4; g++)
#pragma unroll
            for (int mp = 0; mp < 4; mp++) acc[g][mp] = b1p[g];
        for (int tb = 0; tb < 32; tb++) {
            CP_WAIT2();
            __syncthreads();
            if (p < tiles_total) stage_tile(ring, p & (NSLOT - 1), r, tid);
            CP_COMMIT();
            p++; r = (r == TPS - 1) ? 0 : r + 1;
            const float* wb  = ring + (cons & (NSLOT - 1)) * TILE_F + jg;
            const float* act = (tb < 16) ? h0w + tb * KT * MB
                                         : h1r + (tb - 16) * KT * MB;
            accum_tile(acc, wb, act, m0);
            cons++;
        }

        // prefetch next encoder x (shX readers done in phase A; next read is after a sync)
        if (t + 1 < TT && tid < IN_D * MB) {
            int m = tid >> 3, ii = tid & 7;
            shX[ii * MB + m] = x[((size_t)(b0 + m) * TT + (t + 1)) * IN_D + ii];
        }

        cell_epi(acc, c1r, h1w, m0, jg, shHN, bns, bnh, dec);

        if (dec) {
            int d = t - TT;
            __syncthreads();   // HN visible
            // FC1: relu(BN(h1) @ W1^T + b1) -> shO1[m][64]
#pragma unroll
            for (int i = 0; i < (MB * FCH) / NTHR; i++) {
                int idx = tid + i * NTHR;
                int m = idx >> 6, n = idx & 63;
                float s = b1fc[n];
#pragma unroll 8
                for (int k = 0; k < H; k++) s += shHN[k * MB + m] * shW1[k * FCH + n];
                shO1[idx] = fmaxf(s, 0.f);
            }
            __syncthreads();
            // FC2 + output write
            if (tid < MB * OUTD) {
                int m = tid >> 2, o = tid & 3;
                float s = b2[o];
#pragma unroll 8
                for (int k = 0; k < FCH; k++) s += shO1[m * FCH + k] * W2[o * FCH + k];
                shO2[tid] = s;
                out[((size_t)(b0 + m) * steps + d) * OUTD + o] = s;
            }
            __syncthreads();
            // feedback: xin = out @ Wf^T + bf -> shX (transposed)
            if (tid < IN_D * MB) {
                int m = tid >> 3, i = tid & 7;
                float s = bf[i];
#pragma unroll
                for (int o = 0; o < OUTD; o++) s += shO2[m * OUTD + o] * Wf[i * OUTD + o];
                shX[i * MB + m] = s;
            }
            // next phase-A tile sync orders these writes before reads
        }

        float* tmp;
        tmp = h0r; h0r = h0w; h0w = tmp;
        tmp = h1r; h1r = h1w; h1w = tmp;
    }
}

extern "C" void kernel_launch(void* const* d_in, const int* in_sizes, int n_in,
                              void* d_out, int out_size) {
    const float* x    = (const float*)d_in[0];
    const float* Wih0 = (const float*)d_in[1];
    const float* Whh0 = (const float*)d_in[2];
    const float* bih0 = (const float*)d_in[3];
    const float* bhh0 = (const float*)d_in[4];
    const float* Wih1 = (const float*)d_in[5];
    const float* Whh1 = (const float*)d_in[6];
    const float* bih1 = (const float*)d_in[7];
    const float* bhh1 = (const float*)d_in[8];
    const float* gam  = (const float*)d_in[9];
    const float* bet  = (const float*)d_in[10];
    const float* mean = (const float*)d_in[11];
    const float* var  = (const float*)d_in[12];
    const float* W1   = (const float*)d_in[13];
    const float* b1   = (const float*)d_in[14];
    const float* W2   = (const float*)d_in[15];
    const float* b2   = (const float*)d_in[16];
    const float* Wf   = (const float*)d_in[17];
    const float* bf   = (const float*)d_in[18];
    float* out = (float*)d_out;

    int B = in_sizes[0] / (TT * IN_D);
    int steps = out_size / (B * OUTD);

    cudaFuncSetAttribute(lstm_main, cudaFuncAttributeMaxDynamicSharedMemorySize,
                         SM_TOT * sizeof(float));

    prep_kernel<<<256, 256>>>(Wih0, Whh0, bih0, bhh0, Wih1, Whh1, bih1, bhh1,
                              gam, bet, mean, var, W1);
    lstm_main<<<B / MB, NTHR, SM_TOT * sizeof(float)>>>(x, W2, b2, Wf, bf, b1, out, steps);
}

// round 8
// speedup vs baseline: 1.6188x; 1.1903x over previous
#include <cuda_runtime.h>

#define H     128
#define IN_D  8
#define TT    512
#define OUTD  4
#define FCH   64
#define MB    32
#define NTHR  512
#define APAD  40                  // activation row stride (conflict-free A frags)
#define HNP   33                  // shHN row stride
#define LBLK  36                  // floats per lane block (32 data + 4 pad)
#define JBLK  (32 * LBLK)         // 1152 floats per (tile, j-group)
#define SLOT_F (8 * JBLK)         // 9216 floats per weight tile (8 j-groups)
#define NSLOT 3
#define TPS   49                  // tiles/step: 1 (Wih0) + 16 + 16 + 16

// permuted hi/lo tf32 weights, fragment-ordered per lane
__device__ __align__(16) float g_Wperm[TPS * SLOT_F];
__device__ __align__(16) float g_W1T[H * FCH];
__device__ float g_b0[512];
__device__ float g_b1[512];
__device__ float g_bnsc[H];
__device__ float g_bnsh[H];

__device__ __forceinline__ unsigned f2tf32(float f) {
    unsigned u; asm("cvt.rna.tf32.f32 %0, %1;" : "=r"(u) : "f"(f)); return u;
}
__device__ __forceinline__ float tf32f(float f) { return __uint_as_float(f2tf32(f)); }

__global__ void prep_kernel(const float* __restrict__ Wih0, const float* __restrict__ Whh0,
                            const float* __restrict__ bih0, const float* __restrict__ bhh0,
                            const float* __restrict__ Wih1, const float* __restrict__ Whh1,
                            const float* __restrict__ bih1, const float* __restrict__ bhh1,
                            const float* __restrict__ gam,  const float* __restrict__ bet,
                            const float* __restrict__ mean, const float* __restrict__ var,
                            const float* __restrict__ W1)
{
    int i0 = blockIdx.x * blockDim.x + threadIdx.x;
    int st = gridDim.x * blockDim.x;

    // permuted hi/lo weights: idx over (r, jg, lane, f)
    for (int idx = i0; idx < TPS * 8 * 32 * 8; idx += st) {
        int f    = idx & 7;
        int lane = (idx >> 3) & 31;
        int jg   = (idx >> 8) & 7;
        int r    = idx >> 11;
        int laneK = lane & 3, laneM = lane >> 2;
        int g = f >> 1, pp = f & 1;
        int n = g * H + jg * 16 + pp * 8 + laneM;     // output column 0..511
        float w0, w1;
        if (r == 0) {
            w0 = Wih0[n * IN_D + laneK];
            w1 = Wih0[n * IN_D + laneK + 4];
        } else if (r <= 16) {
            int k = (r - 1) * 8 + laneK;
            w0 = Whh0[n * H + k]; w1 = Whh0[n * H + k + 4];
        } else if (r <= 32) {
            int k = (r - 17) * 8 + laneK;
            w0 = Wih1[n * H + k]; w1 = Wih1[n * H + k + 4];
        } else {
            int k = (r - 33) * 8 + laneK;
            w0 = Whh1[n * H + k]; w1 = Whh1[n * H + k + 4];
        }
        float h0 = tf32f(w0), h1 = tf32f(w1);
        float l0 = tf32f(w0 - h0), l1 = tf32f(w1 - h1);
        int base = ((r * 8 + jg) * 32 + lane) * LBLK;
        int off  = g * 4 + pp * 2;          // chunk g holds frags (g,0) and (g,1)
        g_Wperm[base + off]          = h0;
        g_Wperm[base + off + 1]      = h1;
        g_Wperm[base + 16 + off]     = l0;
        g_Wperm[base + 16 + off + 1] = l1;
    }
    for (int idx = i0; idx < 512; idx += st) {
        g_b0[idx] = bih0[idx] + bhh0[idx];
        g_b1[idx] = bih1[idx] + bhh1[idx];
    }
    for (int idx = i0; idx < H * FCH; idx += st) {
        int k = idx / FCH, j = idx % FCH;
        g_W1T[idx] = W1[j * H + k];
    }
    for (int idx = i0; idx < H; idx += st) {
        float s = gam[idx] * rsqrtf(var[idx] + 1e-5f);
        g_bnsc[idx] = s;
        g_bnsh[idx] = bet[idx] - mean[idx] * s;
    }
}

__device__ __forceinline__ float sigm(float v)  { return __fdividef(1.f, 1.f + __expf(-v)); }
__device__ __forceinline__ float tanhh(float v) { return 2.f * __fdividef(1.f, 1.f + __expf(-2.f * v)) - 1.f; }

__device__ __forceinline__ unsigned smem_u32(const void* p) {
    return (unsigned)__cvta_generic_to_shared(p);
}
#define CP_COMMIT() asm volatile("cp.async.commit_group;" ::: "memory")
#define CP_WAIT1()  asm volatile("cp.async.wait_group 1;"  ::: "memory")

__device__ __forceinline__ void stage_tile(float* __restrict__ ring, int slot, int r, int tid) {
    const float* src = g_Wperm + (size_t)r * SLOT_F;
    unsigned ds = smem_u32(ring + slot * SLOT_F);
#pragma unroll
    for (int i = 0; i < 5; i++) {
        int c = tid + i * NTHR;
        if (c < SLOT_F / 4)
            asm volatile("cp.async.cg.shared.global [%0], [%1], 16;"
                         :: "r"(ds + c * 16), "l"(src + c * 4));
    }
}

__device__ __forceinline__ void mma8(float* d, unsigned a0, unsigned a1, unsigned a2, unsigned a3,
                                     unsigned b0, unsigned b1) {
    asm volatile("mma.sync.aligned.m16n8k8.row.col.f32.tf32.tf32.f32 "
                 "{%0,%1,%2,%3}, {%4,%5,%6,%7}, {%8,%9}, {%0,%1,%2,%3};"
                 : "+f"(d[0]), "+f"(d[1]), "+f"(d[2]), "+f"(d[3])
                 : "r"(a0), "r"(a1), "r"(a2), "r"(a3), "r"(b0), "r"(b1));
}

// one 8-k tile, 3xTF32 compensated. acc[f=g*2+pp][4]
__device__ __forceinline__ void mma_tile(float (&acc)[8][4],
                                         const float* __restrict__ bb,
                                         const float* __restrict__ aH,
                                         const float* __restrict__ aL)
{
    unsigned h0 = __float_as_uint(aH[0]);
    unsigned h1 = __float_as_uint(aH[8]);
    unsigned h2 = __float_as_uint(aH[4 * APAD]);
    unsigned h3 = __float_as_uint(aH[4 * APAD + 8]);
    unsigned l0 = __float_as_uint(aL[0]);
    unsigned l1 = __float_as_uint(aL[8]);
    unsigned l2 = __float_as_uint(aL[4 * APAD]);
    unsigned l3 = __float_as_uint(aL[4 * APAD + 8]);
#pragma unroll
    for (int c = 0; c < 4; c++) {
        float4 bh = *reinterpret_cast<const float4*>(bb + c * 4);
        float4 bl = *reinterpret_cast<const float4*>(bb + 16 + c * 4);
        unsigned bhx = __float_as_uint(bh.x), bhy = __float_as_uint(bh.y);
        unsigned bhz = __float_as_uint(bh.z), bhw = __float_as_uint(bh.w);
        unsigned blx = __float_as_uint(bl.x), bly = __float_as_uint(bl.y);
        unsigned blz = __float_as_uint(bl.z), blw = __float_as_uint(bl.w);
        mma8(acc[2 * c],     h0, h1, h2, h3, bhx, bhy);
        mma8(acc[2 * c],     l0, l1, l2, l3, bhx, bhy);
        mma8(acc[2 * c],     h0, h1, h2, h3, blx, bly);
        mma8(acc[2 * c + 1], h0, h1, h2, h3, bhz, bhw);
        mma8(acc[2 * c + 1], l0, l1, l2, l3, bhz, bhw);
        mma8(acc[2 * c + 1], h0, h1, h2, h3, blz, blw);
    }
}

__device__ __forceinline__ void acc_bias(float (&acc)[8][4], const float* __restrict__ shB,
                                         int j0, int laneK)
{
#pragma unroll
    for (int f = 0; f < 8; f++) {
        int g = f >> 1, pp = f & 1;
        float2 b = *reinterpret_cast<const float2*>(shB + g * H + j0 + pp * 8 + 2 * laneK);
        acc[f][0] = b.x; acc[f][1] = b.y; acc[f][2] = b.x; acc[f][3] = b.y;
    }
}

__device__ __forceinline__ void epilogue(float (&acc)[8][4], float* cst,
                                         float* __restrict__ hH, float* __restrict__ hL,
                                         float* __restrict__ hn,
                                         const float2* bns, const float2* bnh, bool wantHN,
                                         int laneK, int laneM, int mbase, int j0)
{
#pragma unroll
    for (int pp = 0; pp < 2; pp++) {
#pragma unroll
        for (int q = 0; q < 4; q++) {
            float zi = acc[0 + pp][q], zf = acc[2 + pp][q];
            float zg = acc[4 + pp][q], zo = acc[6 + pp][q];
            float c = sigm(zf) * cst[pp * 4 + q] + sigm(zi) * tanhh(zg);
            cst[pp * 4 + q] = c;
            float h = sigm(zo) * tanhh(c);
            int j = j0 + pp * 8 + 2 * laneK + (q & 1);
            int m = mbase + laneM + ((q >> 1) * 8);
            float hh = tf32f(h);
            hH[j * APAD + m] = hh;
            hL[j * APAD + m] = tf32f(h - hh);
            if (wantHN) {
                float s  = (q & 1) ? bns[pp].y : bns[pp].x;
                float sh = (q & 1) ? bnh[pp].y : bnh[pp].x;
                hn[j * HNP + m] = h * s + sh;
            }
        }
    }
}

// smem layout (floats)
#define SM_XH   (NSLOT * SLOT_F)
#define SM_XL   (SM_XH + IN_D * APAD)
#define SM_H0H  (SM_XL + IN_D * APAD)
#define SM_H0L  (SM_H0H + H * APAD)
#define SM_H1H  (SM_H0L + H * APAD)
#define SM_H1L  (SM_H1H + H * APAD)
#define SM_HN   (SM_H1L + H * APAD)
#define SM_B0   (SM_HN + H * HNP)
#define SM_B1   (SM_B0 + 512)
#define SM_O1   (SM_B1 + 512)
#define SM_O2   (SM_O1 + MB * FCH)
#define SM_TOT  (SM_O2 + MB * OUTD)

__global__ void __launch_bounds__(NTHR, 1)
lstm_main(const float* __restrict__ x,
          const float* __restrict__ W2, const float* __restrict__ b2,
          const float* __restrict__ Wf, const float* __restrict__ bf,
          const float* __restrict__ b1fc,
          float* __restrict__ out, int steps)
{
    extern __shared__ float sm[];
    float* ring = sm;
    float* shXH = sm + SM_XH;
    float* shXL = sm + SM_XL;
    float* shH0H = sm + SM_H0H;
    float* shH0L = sm + SM_H0L;
    float* shH1H = sm + SM_H1H;
    float* shH1L = sm + SM_H1L;
    float* shHN = sm + SM_HN;
    float* shB0 = sm + SM_B0;
    float* shB1 = sm + SM_B1;
    float* shO1 = sm + SM_O1;
    float* shO2 = sm + SM_O2;

    const int tid   = threadIdx.x;
    const int wid   = tid >> 5;
    const int lane  = tid & 31;
    const int laneK = lane & 3;
    const int laneM = lane >> 2;
    const int mbase = (wid & 1) * 16;
    const int jg    = wid >> 1;
    const int j0    = jg * 16;
    const int b0    = blockIdx.x * MB;
    const int aoff  = laneK * APAD + mbase + laneM;
    const int boff  = jg * JBLK + lane * LBLK;

    for (int i = tid; i < 4 * H * APAD; i += NTHR) shH0H[i] = 0.f;
    for (int i = tid; i < 512; i += NTHR) { shB0[i] = g_b0[i]; shB1[i] = g_b1[i]; }

    float2 bns[2], bnh[2];
#pragma unroll
    for (int pp = 0; pp < 2; pp++) {
        bns[pp] = *reinterpret_cast<const float2*>(g_bnsc + j0 + pp * 8 + 2 * laneK);
        bnh[pp] = *reinterpret_cast<const float2*>(g_bnsh + j0 + pp * 8 + 2 * laneK);
    }

    float cst0[8], cst1[8];
#pragma unroll
    for (int i = 0; i < 8; i++) { cst0[i] = 0.f; cst1[i] = 0.f; }

    if (tid < IN_D * MB) {
        int m = tid >> 3, ii = tid & 7;
        float v = x[((size_t)(b0 + m) * TT + 0) * IN_D + ii];
        float hh = tf32f(v);
        shXH[ii * APAD + m] = hh;
        shXL[ii * APAD + m] = tf32f(v - hh);
    }

    const int total = TT + steps;
    const int tiles_total = total * TPS;

    int p = 0, pr = 0, pslot = 0, cslot = 0;
#pragma unroll
    for (int i = 0; i < 2; i++) {
        stage_tile(ring, pslot, pr, tid);
        CP_COMMIT();
        p++; pr++; pslot++;
    }

    for (int t = 0; t < total; t++) {
        bool dec = (t >= TT);
        float acc[8][4];

        // ---------- layer 0: 17 tiles ----------
        acc_bias(acc, shB0, j0, laneK);
        for (int r = 0; r < 17; r++) {
            CP_WAIT1();
            __syncthreads();
            if (p < tiles_total) stage_tile(ring, pslot, pr, tid);
            CP_COMMIT();
            p++;
            pr = (pr == TPS - 1) ? 0 : pr + 1;
            pslot = (pslot == NSLOT - 1) ? 0 : pslot + 1;
            const float* bb = ring + cslot * SLOT_F + boff;
            const float* aH = (r == 0) ? shXH : shH0H + (r - 1) * 8 * APAD;
            const float* aL = (r == 0) ? shXL : shH0L + (r - 1) * 8 * APAD;
            mma_tile(acc, bb, aH + aoff, aL + aoff);
            cslot = (cslot == NSLOT - 1) ? 0 : cslot + 1;
        }
        __syncthreads();    // all reads of old h0 done
        epilogue(acc, cst0, shH0H, shH0L, shHN, bns, bnh, false, laneK, laneM, mbase, j0);

        // ---------- layer 1: 32 tiles ----------
        acc_bias(acc, shB1, j0, laneK);
        for (int r = 0; r < 32; r++) {
            CP_WAIT1();
            __syncthreads();    // r==0: also publishes new h0
            if (p < tiles_total) stage_tile(ring, pslot, pr, tid);
            CP_COMMIT();
            p++;
            pr = (pr == TPS - 1) ? 0 : pr + 1;
            pslot = (pslot == NSLOT - 1) ? 0 : pslot + 1;
            const float* bb = ring + cslot * SLOT_F + boff;
            const float* aH = (r < 16) ? shH0H + r * 8 * APAD : shH1H + (r - 16) * 8 * APAD;
            const float* aL = (r < 16) ? shH0L + r * 8 * APAD : shH1L + (r - 16) * 8 * APAD;
            mma_tile(acc, bb, aH + aoff, aL + aoff);
            cslot = (cslot == NSLOT - 1) ? 0 : cslot + 1;
        }
        __syncthreads();    // all reads of old h1 done
        epilogue(acc, cst1, shH1H, shH1L, shHN, bns, bnh, dec, laneK, laneM, mbase, j0);

        if (dec) {
            int d = t - TT;
            __syncthreads();    // shHN visible
#pragma unroll
            for (int i = 0; i < (MB * FCH) / NTHR; i++) {
                int idx = tid + i * NTHR;
                int m = idx >> 6, n = idx & 63;
                float s = b1fc[n];
#pragma unroll 8
                for (int k = 0; k < H; k++) s += shHN[k * HNP + m] * g_W1T[k * FCH + n];
                shO1[idx] = fmaxf(s, 0.f);
            }
            __syncthreads();
            if (tid < MB * OUTD) {
                int m = tid >> 2, o = tid & 3;
                float s = b2[o];
#pragma unroll 8
                for (int k = 0; k < FCH; k++) s += shO1[m * FCH + k] * W2[o * FCH + k];
                shO2[tid] = s;
                out[((size_t)(b0 + m) * steps + d) * OUTD + o] = s;
            }
            __syncthreads();
            if (tid < IN_D * MB) {
                int m = tid >> 3, ii = tid & 7;
                float s = bf[ii];
#pragma unroll
                for (int o = 0; o < OUTD; o++) s += shO2[m * OUTD + o] * Wf[ii * OUTD + o];
                float hh = tf32f(s);
                shXH[ii * APAD + m] = hh;
                shXL[ii * APAD + m] = tf32f(s - hh);
            }
        } else if (t + 1 < TT) {
            if (tid < IN_D * MB) {
                int m = tid >> 3, ii = tid & 7;
                float v = x[((size_t)(b0 + m) * TT + (t + 1)) * IN_D + ii];
                float hh = tf32f(v);
                shXH[ii * APAD + m] = hh;
                shXL[ii * APAD + m] = tf32f(v - hh);
            }
        }
        // next step's first tile sync orders shX writes before reads
    }
}

extern "C" void kernel_launch(void* const* d_in, const int* in_sizes, int n_in,
                              void* d_out, int out_size) {
    const float* x    = (const float*)d_in[0];
    const float* Wih0 = (const float*)d_in[1];
    const float* Whh0 = (const float*)d_in[2];
    const float* bih0 = (const float*)d_in[3];
    const float* bhh0 = (const float*)d_in[4];
    const float* Wih1 = (const float*)d_in[5];
    const float* Whh1 = (const float*)d_in[6];
    const float* bih1 = (const float*)d_in[7];
    const float* bhh1 = (const float*)d_in[8];
    const float* gam  = (const float*)d_in[9];
    const float* bet  = (const float*)d_in[10];
    const float* mean = (const float*)d_in[11];
    const float* var  = (const float*)d_in[12];
    const float* W1   = (const float*)d_in[13];
    const float* b1   = (const float*)d_in[14];
    const float* W2   = (const float*)d_in[15];
    const float* b2   = (const float*)d_in[16];
    const float* Wf   = (const float*)d_in[17];
    const float* bf   = (const float*)d_in[18];
    float* out = (float*)d_out;

    int B = in_sizes[0] / (TT * IN_D);
    int steps = out_size / (B * OUTD);

    cudaFuncSetAttribute(lstm_main, cudaFuncAttributeMaxDynamicSharedMemorySize,
                         SM_TOT * sizeof(float));

    prep_kernel<<<256, 256>>>(Wih0, Whh0, bih0, bhh0, Wih1, Whh1, bih1, bhh1,
                              gam, bet, mean, var, W1);
    lstm_main<<<B / MB, NTHR, SM_TOT * sizeof(float)>>>(x, W2, b2, Wf, bf, b1, out, steps);
}

// round 10
// speedup vs baseline: 2.0621x; 1.2739x over previous
#include <cuda_runtime.h>
#include <cuda_bf16.h>

#define H      128
#define IN_D   8
#define TT     512
#define OUTD   4
#define FCH    64
#define MB     32
#define NTHR   512
#define NCHUNK 25               // weight chunks per step: 1(x,k8) + 8 + 8 + 8 (k16 each)
#define LANEU  20               // u32 per lane block in ring (16 data + 4 pad)
#define SLOTU  (32 * LANEU)     // 640 u32 per warp-slot
#define NSLOT  4
#define APW    40               // u32 row stride of activation buffers (32 + 8 pad)

typedef unsigned u32;

// weights permuted to per-(chunk, warp, lane) fragment order, bf16 hi/lo packed
__device__ u32   g_Wperm[NCHUNK * 16 * 32 * 16];   // 800KB
__device__ float g_W1T[H * FCH];
__device__ float g_b0[512], g_b1[512], g_bnsc[H], g_bnsh[H];

__global__ void prep_kernel(const float* __restrict__ Wih0, const float* __restrict__ Whh0,
                            const float* __restrict__ bih0, const float* __restrict__ bhh0,
                            const float* __restrict__ Wih1, const float* __restrict__ Whh1,
                            const float* __restrict__ bih1, const float* __restrict__ bhh1,
                            const float* __restrict__ gam,  const float* __restrict__ bet,
                            const float* __restrict__ mean, const float* __restrict__ var,
                            const float* __restrict__ W1)
{
    int i0 = blockIdx.x * blockDim.x + threadIdx.x;
    int st = gridDim.x * blockDim.x;

    for (int idx = i0; idx < NCHUNK * 16 * 32 * 16; idx += st) {
        int s16  = idx & 15;
        int lane = (idx >> 4) & 31;
        int w    = (idx >> 9) & 15;
        int r    = idx >> 13;
        int laneK = lane & 3, laneM = lane >> 2;
        int g = s16 >> 2, part = s16 & 3;
        int n = g * 128 + w * 8 + laneM;            // output column 0..511
        int kk = 2 * laneK + ((part & 1) ? 8 : 0);  // k within chunk
        bool isLo = (part >= 2);
        const float* Wm; int K, kb;
        if (r == 0)       { Wm = Wih0; K = IN_D; kb = 0; }
        else if (r <= 8)  { Wm = Whh0; K = H; kb = (r - 1)  * 16; }
        else if (r <= 16) { Wm = Wih1; K = H; kb = (r - 9)  * 16; }
        else              { Wm = Whh1; K = H; kb = (r - 17) * 16; }
        u32 val = 0;
        if (kb + kk + 1 < K || (kb + kk + 1 == K - 0 && kb + kk < K)) { /* guarded below */ }
        if (kb + kk < K) {
            float w0 = Wm[n * K + kb + kk];
            float w1 = Wm[n * K + kb + kk + 1];
            __nv_bfloat16 hb0 = __float2bfloat16_rn(w0);
            __nv_bfloat16 hb1 = __float2bfloat16_rn(w1);
            __nv_bfloat162 pk;
            if (isLo) {
                float l0 = w0 - __bfloat162float(hb0);
                float l1 = w1 - __bfloat162float(hb1);
                pk = __floats2bfloat162_rn(l0, l1);
            } else {
                pk.x = hb0; pk.y = hb1;
            }
            val = *reinterpret_cast<u32*>(&pk);
        }
        g_Wperm[idx] = val;
    }
    for (int idx = i0; idx < 512; idx += st) {
        g_b0[idx] = bih0[idx] + bhh0[idx];
        g_b1[idx] = bih1[idx] + bhh1[idx];
    }
    for (int idx = i0; idx < H * FCH; idx += st) {
        int k = idx / FCH, j = idx % FCH;
        g_W1T[idx] = W1[j * H + k];
    }
    for (int idx = i0; idx < H; idx += st) {
        float s = gam[idx] * rsqrtf(var[idx] + 1e-5f);
        g_bnsc[idx] = s;
        g_bnsh[idx] = bet[idx] - mean[idx] * s;
    }
}

__device__ __forceinline__ float sigm(float v)  { return __fdividef(1.f, 1.f + __expf(-v)); }
__device__ __forceinline__ float tanhh(float v) { return 2.f * __fdividef(1.f, 1.f + __expf(-2.f * v)) - 1.f; }

__device__ __forceinline__ unsigned smem_u32(const void* p) {
    return (unsigned)__cvta_generic_to_shared(p);
}

__device__ __forceinline__ void pack_hilo(float a, float b, u32* ph, u32* pl) {
    __nv_bfloat16 ha = __float2bfloat16_rn(a), hb = __float2bfloat16_rn(b);
    __nv_bfloat162 hh; hh.x = ha; hh.y = hb;
    *ph = *reinterpret_cast<u32*>(&hh);
    float la = a - __bfloat162float(ha), lb = b - __bfloat162float(hb);
    __nv_bfloat162 ll = __floats2bfloat162_rn(la, lb);
    *pl = *reinterpret_cast<u32*>(&ll);
}

__device__ __forceinline__ void mma16(float* d, u32 a0, u32 a1, u32 a2, u32 a3, u32 b0, u32 b1) {
    asm volatile("mma.sync.aligned.m16n8k16.row.col.f32.bf16.bf16.f32 "
                 "{%0,%1,%2,%3},{%4,%5,%6,%7},{%8,%9},{%0,%1,%2,%3};"
                 : "+f"(d[0]), "+f"(d[1]), "+f"(d[2]), "+f"(d[3])
                 : "r"(a0), "r"(a1), "r"(a2), "r"(a3), "r"(b0), "r"(b1));
}
__device__ __forceinline__ void mma8b(float* d, u32 a0, u32 a1, u32 b0) {
    asm volatile("mma.sync.aligned.m16n8k8.row.col.f32.bf16.bf16.f32 "
                 "{%0,%1,%2,%3},{%4,%5},{%6},{%0,%1,%2,%3};"
                 : "+f"(d[0]), "+f"(d[1]), "+f"(d[2]), "+f"(d[3])
                 : "r"(a0), "r"(a1), "r"(b0));
}

// stage one warp-private 2KB weight chunk (4 x 16B per lane)
__device__ __forceinline__ void stage_chunk(u32* __restrict__ ringw, int slot, int r,
                                            int wid, int lane) {
    const uint4* src = reinterpret_cast<const uint4*>(g_Wperm) + (((r * 16 + wid) * 32 + lane) << 2);
    unsigned ds = smem_u32(ringw + slot * SLOTU + lane * LANEU);
#pragma unroll
    for (int i = 0; i < 4; i++)
        asm volatile("cp.async.cg.shared.global [%0], [%1], 16;" :: "r"(ds + i * 16), "l"(src + i));
}

// one k16 chunk: 2 m-halves x 4 gates x 3 compensation terms = 24 MMAs
__device__ __forceinline__ void chunk16(float (&acc)[2][4][4], const u32* __restrict__ bb,
                                        const u32* __restrict__ aH, const u32* __restrict__ aL,
                                        int laneK, int laneM) {
#pragma unroll
    for (int h = 0; h < 2; h++) {
        const u32* pH = aH + laneK * APW + h * 16 + laneM;
        const u32* pL = aL + laneK * APW + h * 16 + laneM;
        u32 a0 = pH[0], a1 = pH[8], a2 = pH[4 * APW], a3 = pH[4 * APW + 8];
        u32 l0 = pL[0], l1 = pL[8], l2 = pL[4 * APW], l3 = pL[4 * APW + 8];
#pragma unroll
        for (int g = 0; g < 4; g++) {
            uint4 b = *reinterpret_cast<const uint4*>(bb + g * 4);
            mma16(acc[h][g], a0, a1, a2, a3, b.x, b.y);
            mma16(acc[h][g], l0, l1, l2, l3, b.x, b.y);
            mma16(acc[h][g], a0, a1, a2, a3, b.z, b.w);
        }
    }
}

// x chunk (k=8)
__device__ __forceinline__ void chunk8(float (&acc)[2][4][4], const u32* __restrict__ bb,
                                       const u32* __restrict__ aH, const u32* __restrict__ aL,
                                       int laneK, int laneM) {
#pragma unroll
    for (int h = 0; h < 2; h++) {
        const u32* pH = aH + laneK * APW + h * 16 + laneM;
        const u32* pL = aL + laneK * APW + h * 16 + laneM;
        u32 a0 = pH[0], a1 = pH[8];
        u32 l0 = pL[0], l1 = pL[8];
#pragma unroll
        for (int g = 0; g < 4; g++) {
            uint4 b = *reinterpret_cast<const uint4*>(bb + g * 4);
            mma8b(acc[h][g], a0, a1, b.x);
            mma8b(acc[h][g], l0, l1, b.x);
            mma8b(acc[h][g], a0, a1, b.z);
        }
    }
}

__device__ __forceinline__ void acc_init(float (&acc)[2][4][4], const float* __restrict__ shB,
                                         int wid, int laneK) {
    int j = wid * 8 + 2 * laneK;
#pragma unroll
    for (int g = 0; g < 4; g++) {
        float bj  = shB[g * 128 + j];
        float bj1 = shB[g * 128 + j + 1];
#pragma unroll
        for (int h = 0; h < 2; h++) {
            acc[h][g][0] = bj; acc[h][g][1] = bj1;
            acc[h][g][2] = bj; acc[h][g][3] = bj1;
        }
    }
}

// LSTM gates + state update; h written as packed bf16 hi/lo
__device__ __forceinline__ void epilogue(float (&acc)[2][4][4], float* cst,
                                         u32* __restrict__ hHb, u32* __restrict__ hLb,
                                         int wid, int laneK, int laneM) {
    int jp = wid * 4 + laneK;      // kpair row index of this thread's (j, j+1)
#pragma unroll
    for (int h = 0; h < 2; h++) {
#pragma unroll
        for (int rr = 0; rr < 2; rr++) {
            int m = h * 16 + laneM + rr * 8;
            float hv[2];
#pragma unroll
            for (int q = 0; q < 2; q++) {
                float zi = acc[h][0][rr * 2 + q], zf = acc[h][1][rr * 2 + q];
                float zg = acc[h][2][rr * 2 + q], zo = acc[h][3][rr * 2 + q];
                int ci = h * 4 + rr * 2 + q;
                float c = sigm(zf) * cst[ci] + sigm(zi) * tanhh(zg);
                cst[ci] = c;
                hv[q] = sigm(zo) * tanhh(c);
            }
            pack_hilo(hv[0], hv[1], &hHb[jp * APW + m], &hLb[jp * APW + m]);
        }
    }
}

// smem (u32 units)
#define SM_RING 0
#define SM_XH   (16 * NSLOT * SLOTU)        // 40960
#define SM_XL   (SM_XH + 4 * APW)
#define SM_H0H  (SM_XL + 4 * APW)
#define SM_H0L  (SM_H0H + 64 * APW)
#define SM_H1H  (SM_H0L + 64 * APW)
#define SM_H1L  (SM_H1H + 64 * APW)
#define SM_FLT  (SM_H1L + 64 * APW)         // float region starts here
#define NFLT    (512 + 512 + 128 + 128 + MB * FCH + MB * OUTD)
#define SM_TOTB ((SM_FLT + NFLT) * 4)

__global__ void __launch_bounds__(NTHR, 1)
lstm_main(const float* __restrict__ x,
          const float* __restrict__ W2, const float* __restrict__ b2,
          const float* __restrict__ Wf, const float* __restrict__ bf,
          const float* __restrict__ b1fc,
          float* __restrict__ out, int steps)
{
    extern __shared__ u32 smu[];
    u32* ring = smu + SM_RING;
    u32* xH  = smu + SM_XH;
    u32* xL  = smu + SM_XL;
    u32* h0H = smu + SM_H0H;
    u32* h0L = smu + SM_H0L;
    u32* h1H = smu + SM_H1H;
    u32* h1L = smu + SM_H1L;
    float* shB0  = (float*)(smu + SM_FLT);
    float* shB1  = shB0 + 512;
    float* shBNs = shB1 + 512;
    float* shBNh = shBNs + 128;
    float* shO1  = shBNh + 128;
    float* shO2  = shO1 + MB * FCH;

    const int tid  = threadIdx.x;
    const int wid  = tid >> 5, lane = tid & 31;
    const int laneK = lane & 3, laneM = lane >> 2;
    const int b0 = blockIdx.x * MB;
    u32* ringw = ring + wid * (NSLOT * SLOTU);

    // zero activation buffers (contiguous), stage constants
    for (int i = tid; i < 8 * APW + 4 * 64 * APW; i += NTHR) xH[i] = 0;
    for (int i = tid; i < 512; i += NTHR) { shB0[i] = g_b0[i]; shB1[i] = g_b1[i]; }
    if (tid < H) { shBNs[tid] = g_bnsc[tid]; shBNh[tid] = g_bnsh[tid]; }

    float cst0[8], cst1[8];
#pragma unroll
    for (int i = 0; i < 8; i++) { cst0[i] = 0.f; cst1[i] = 0.f; }

    // stage x[0]
    if (tid < 128) {
        int kp = tid >> 5, m = tid & 31;
        const float* xp = x + ((size_t)(b0 + m) * TT + 0) * IN_D + 2 * kp;
        pack_hilo(xp[0], xp[1], &xH[kp * APW + m], &xL[kp * APW + m]);
    }
    __syncthreads();

    const int total = TT + steps;
    const int tiles_total = total * NCHUNK;
    int p = 0, pr = 0, cs = 0;
#pragma unroll
    for (int i = 0; i < 3; i++) {
        stage_chunk(ringw, i, pr, wid, lane);
        asm volatile("cp.async.commit_group;" ::: "memory");
        p++; pr++;
    }

#define PIPE() do { \
    asm volatile("cp.async.wait_group 2;" ::: "memory"); \
    if (p < tiles_total) { \
        stage_chunk(ringw, p & 3, pr, wid, lane); \
        asm volatile("cp.async.commit_group;" ::: "memory"); \
    } \
    p++; pr = (pr == NCHUNK - 1) ? 0 : pr + 1; \
} while (0)

    for (int t = 0; t < total; t++) {
        bool dec = (t >= TT);
        float acc[2][4][4];

        // ---------------- layer 0: x chunk + 8 h0 chunks ----------------
        acc_init(acc, shB0, wid, laneK);
        PIPE();
        chunk8(acc, ringw + cs * SLOTU + lane * LANEU, xH, xL, laneK, laneM);
        cs = (cs + 1) & 3;
#pragma unroll
        for (int r = 0; r < 8; r++) {
            PIPE();
            chunk16(acc, ringw + cs * SLOTU + lane * LANEU,
                    h0H + r * 8 * APW, h0L + r * 8 * APW, laneK, laneM);
            cs = (cs + 1) & 3;
        }
        __syncthreads();                 // all warps done reading x, h0(old)
        epilogue(acc, cst0, h0H, h0L, wid, laneK, laneM);
        // stage next encoder x while we're between barriers (x readers all done)
        if (!dec && t + 1 < TT && tid < 128) {
            int kp = tid >> 5, m = tid & 31;
            const float* xp = x + ((size_t)(b0 + m) * TT + (t + 1)) * IN_D + 2 * kp;
            pack_hilo(xp[0], xp[1], &xH[kp * APW + m], &xL[kp * APW + m]);
        }
        __syncthreads();                 // h0(new) + x(next) published

        // ---------------- layer 1: 8 h0 chunks + 8 h1 chunks ----------------
        acc_init(acc, shB1, wid, laneK);
#pragma unroll
        for (int r = 0; r < 16; r++) {
            PIPE();
            const u32* aH = (r < 8) ? h0H + r * 8 * APW : h1H + (r - 8) * 8 * APW;
            const u32* aL = (r < 8) ? h0L + r * 8 * APW : h1L + (r - 8) * 8 * APW;
            chunk16(acc, ringw + cs * SLOTU + lane * LANEU, aH, aL, laneK, laneM);
            cs = (cs + 1) & 3;
        }
        __syncthreads();                 // all warps done reading h1(old)
        epilogue(acc, cst1, h1H, h1L, wid, laneK, laneM);

        if (dec) {
            int d = t - TT;
            __syncthreads();             // h1(new) visible
            // FC1 with inline BN: relu(BN(h1) @ W1^T + b1)
#pragma unroll
            for (int i = 0; i < (MB * FCH) / NTHR; i++) {
                int idx = tid + i * NTHR;
                int m = idx >> 6, n = idx & 63;
                float s = b1fc[n];
#pragma unroll 4
                for (int kp = 0; kp < 64; kp++) {
                    u32 wh = h1H[kp * APW + m], wl = h1L[kp * APW + m];
                    __nv_bfloat162 bh = *reinterpret_cast<__nv_bfloat162*>(&wh);
                    __nv_bfloat162 bl = *reinterpret_cast<__nv_bfloat162*>(&wl);
                    float ha = __bfloat162float(bh.x) + __bfloat162float(bl.x);
                    float hb = __bfloat162float(bh.y) + __bfloat162float(bl.y);
                    int k0 = 2 * kp;
                    float hn0 = ha * shBNs[k0] + shBNh[k0];
                    float hn1 = hb * shBNs[k0 + 1] + shBNh[k0 + 1];
                    s += hn0 * g_W1T[k0 * FCH + n] + hn1 * g_W1T[(k0 + 1) * FCH + n];
                }
                shO1[idx] = fmaxf(s, 0.f);
            }
            __syncthreads();
            if (tid < MB * OUTD) {
                int m = tid >> 2, o = tid & 3;
                float s = b2[o];
#pragma unroll 8
                for (int k = 0; k < FCH; k++) s += shO1[m * FCH + k] * W2[o * FCH + k];
                shO2[tid] = s;
                out[((size_t)(b0 + m) * steps + d) * OUTD + o] = s;
            }
            __syncthreads();
            // feedback: xin = out @ Wf^T + bf
            if (tid < 128) {
                int kp = tid >> 5, m = tid & 31;
                float s0 = bf[2 * kp], s1 = bf[2 * kp + 1];
#pragma unroll
                for (int o = 0; o < OUTD; o++) {
                    float ov = shO2[m * OUTD + o];
                    s0 += ov * Wf[(2 * kp) * OUTD + o];
                    s1 += ov * Wf[(2 * kp + 1) * OUTD + o];
                }
                pack_hilo(s0, s1, &xH[kp * APW + m], &xL[kp * APW + m]);
            }
            __syncthreads();             // x(next) published before next L0
        }
    }
#undef PIPE
}

extern "C" void kernel_launch(void* const* d_in, const int* in_sizes, int n_in,
                              void* d_out, int out_size) {
    const float* x    = (const float*)d_in[0];
    const float* Wih0 = (const float*)d_in[1];
    const float* Whh0 = (const float*)d_in[2];
    const float* bih0 = (const float*)d_in[3];
    const float* bhh0 = (const float*)d_in[4];
    const float* Wih1 = (const float*)d_in[5];
    const float* Whh1 = (const float*)d_in[6];
    const float* bih1 = (const float*)d_in[7];
    const float* bhh1 = (const float*)d_in[8];
    const float* gam  = (const float*)d_in[9];
    const float* bet  = (const float*)d_in[10];
    const float* mean = (const float*)d_in[11];
    const float* var  = (const float*)d_in[12];
    const float* W1   = (const float*)d_in[13];
    const float* b1   = (const float*)d_in[14];
    const float* W2   = (const float*)d_in[15];
    const float* b2   = (const float*)d_in[16];
    const float* Wf   = (const float*)d_in[17];
    const float* bf   = (const float*)d_in[18];
    float* out = (float*)d_out;

    int B = in_sizes[0] / (TT * IN_D);
    int steps = out_size / (B * OUTD);

    cudaFuncSetAttribute(lstm_main, cudaFuncAttributeMaxDynamicSharedMemorySize, SM_TOTB);

    prep_kernel<<<256, 256>>>(Wih0, Whh0, bih0, bhh0, Wih1, Whh1, bih1, bhh1,
                              gam, bet, mean, var, W1);
    lstm_main<<<B / MB, NTHR, SM_TOTB>>>(x, W2, b2, Wf, bf, b1, out, steps);
}

// round 13
// speedup vs baseline: 4.0484x; 1.9632x over previous
#include <cuda_runtime.h>
#include <cuda_bf16.h>

#define H      128
#define IN_D   8
#define TT     512
#define OUTD   4
#define FCH    64
#define MB     32
#define NTHR   512
#define NCHUNK 25               // weight chunks per step: 1(x,k8) + 8 + 8 + 8 (k16 each)
#define APW    40               // u32 row stride of activation buffers (32 + 8 pad)
#define CHUNKU 8192             // u32 per chunk (32 KB): 16 warps x 32 lanes x 16
#define NSLOT  4

typedef unsigned u32;

// weights permuted to per-(chunk, warp, lane) fragment order, bf16 hi/lo packed,
// uint4-rotated within each lane block for conflict-free LDS.128 without padding
__device__ __align__(128) u32 g_Wperm[NCHUNK * CHUNKU];   // 800KB
__device__ float g_W1T[H * FCH];
__device__ float g_b0[512], g_b1[512], g_bnsc[H], g_bnsh[H];

__global__ void prep_kernel(const float* __restrict__ Wih0, const float* __restrict__ Whh0,
                            const float* __restrict__ bih0, const float* __restrict__ bhh0,
                            const float* __restrict__ Wih1, const float* __restrict__ Whh1,
                            const float* __restrict__ bih1, const float* __restrict__ bhh1,
                            const float* __restrict__ gam,  const float* __restrict__ bet,
                            const float* __restrict__ mean, const float* __restrict__ var,
                            const float* __restrict__ W1)
{
    int i0 = blockIdx.x * blockDim.x + threadIdx.x;
    int st = gridDim.x * blockDim.x;

    for (int idx = i0; idx < NCHUNK * 16 * 32 * 16; idx += st) {
        int part = idx & 3;          // u32 within logical uint4
        int g    = (idx >> 2) & 3;   // logical uint4 index = gate
        int lane = (idx >> 4) & 31;
        int w    = (idx >> 9) & 15;
        int r    = idx >> 13;
        int laneK = lane & 3, laneM = lane >> 2;
        int n = g * 128 + w * 8 + laneM;            // output column 0..511
        int kk = 2 * laneK + ((part & 1) ? 8 : 0);  // k within chunk
        bool isLo = (part >= 2);
        const float* Wm; int K, kb;
        if (r == 0)       { Wm = Wih0; K = IN_D; kb = 0; }
        else if (r <= 8)  { Wm = Whh0; K = H; kb = (r - 1)  * 16; }
        else if (r <= 16) { Wm = Wih1; K = H; kb = (r - 9)  * 16; }
        else              { Wm = Whh1; K = H; kb = (r - 17) * 16; }
        u32 val = 0;
        if (kb + kk < K) {
            float w0 = Wm[n * K + kb + kk];
            float w1 = Wm[n * K + kb + kk + 1];
            __nv_bfloat16 hb0 = __float2bfloat16_rn(w0);
            __nv_bfloat16 hb1 = __float2bfloat16_rn(w1);
            __nv_bfloat162 pk;
            if (isLo) {
                pk = __floats2bfloat162_rn(w0 - __bfloat162float(hb0),
                                           w1 - __bfloat162float(hb1));
            } else {
                pk.x = hb0; pk.y = hb1;
            }
            val = *reinterpret_cast<u32*>(&pk);
        }
        // swizzled placement: logical uint4 g -> physical (g + lane/2) & 3
        int phys = (g + (lane >> 1)) & 3;
        g_Wperm[(((r * 16 + w) * 32 + lane) << 4) + phys * 4 + part] = val;
    }
    for (int idx = i0; idx < 512; idx += st) {
        g_b0[idx] = bih0[idx] + bhh0[idx];
        g_b1[idx] = bih1[idx] + bhh1[idx];
    }
    for (int idx = i0; idx < H * FCH; idx += st) {
        int k = idx / FCH, j = idx % FCH;
        g_W1T[idx] = W1[j * H + k];
    }
    for (int idx = i0; idx < H; idx += st) {
        float s = gam[idx] * rsqrtf(var[idx] + 1e-5f);
        g_bnsc[idx] = s;
        g_bnsh[idx] = bet[idx] - mean[idx] * s;
    }
}

__device__ __forceinline__ float sigm(float v)  { return __fdividef(1.f, 1.f + __expf(-v)); }
__device__ __forceinline__ float tanhh(float v) { return 2.f * __fdividef(1.f, 1.f + __expf(-2.f * v)) - 1.f; }

__device__ __forceinline__ unsigned smem_u32(const void* p) {
    return (unsigned)__cvta_generic_to_shared(p);
}

__device__ __forceinline__ void pack_hilo(float a, float b, u32* ph, u32* pl) {
    __nv_bfloat16 ha = __float2bfloat16_rn(a), hb = __float2bfloat16_rn(b);
    __nv_bfloat162 hh; hh.x = ha; hh.y = hb;
    *ph = *reinterpret_cast<u32*>(&hh);
    __nv_bfloat162 ll = __floats2bfloat162_rn(a - __bfloat162float(ha),
                                              b - __bfloat162float(hb));
    *pl = *reinterpret_cast<u32*>(&ll);
}

// ---- mbarrier / bulk helpers ----
__device__ __forceinline__ void mbar_init(u32 a, u32 cnt) {
    asm volatile("mbarrier.init.shared.b64 [%0], %1;" :: "r"(a), "r"(cnt) : "memory");
}
__device__ __forceinline__ void mbar_expect(u32 a, u32 bytes) {
    asm volatile("mbarrier.arrive.expect_tx.shared.b64 _, [%0], %1;" :: "r"(a), "r"(bytes) : "memory");
}
__device__ __forceinline__ void mbar_wait(u32 a, u32 parity) {
    asm volatile(
        "{\n\t.reg .pred P;\n\t"
        "WL%=:\n\t"
        "mbarrier.try_wait.parity.acquire.cta.shared::cta.b64 P, [%0], %1, 0x989680;\n\t"
        "@P bra WD%=;\n\t"
        "bra WL%=;\n\t"
        "WD%=:\n\t}"
        :: "r"(a), "r"(parity) : "memory");
}
__device__ __forceinline__ void mbar_arrive_rank0(u32 a) {
    asm volatile(
        "{\n\t.reg .b32 ra;\n\t"
        "mapa.shared::cluster.u32 ra, %0, 0;\n\t"
        "mbarrier.arrive.shared::cluster.b64 _, [ra];\n\t}"
        :: "r"(a) : "memory");
}
__device__ __forceinline__ void bulk_mcast(u32 dst, const u32* src, u32 mbar) {
    asm volatile(
        "cp.async.bulk.shared::cluster.global.mbarrier::complete_tx::bytes.multicast::cluster "
        "[%0], [%1], %2, [%3], %4;"
        :: "r"(dst), "l"(src), "r"(32768u), "r"(mbar), "h"((unsigned short)0x3) : "memory");
}
#define CLUSTER_SYNC_() do { \
    asm volatile("barrier.cluster.arrive.aligned;" ::: "memory"); \
    asm volatile("barrier.cluster.wait.aligned;" ::: "memory"); \
} while (0)

__device__ __forceinline__ void mma16(float* d, u32 a0, u32 a1, u32 a2, u32 a3, u32 b0, u32 b1) {
    asm volatile("mma.sync.aligned.m16n8k16.row.col.f32.bf16.bf16.f32 "
                 "{%0,%1,%2,%3},{%4,%5,%6,%7},{%8,%9},{%0,%1,%2,%3};"
                 : "+f"(d[0]), "+f"(d[1]), "+f"(d[2]), "+f"(d[3])
                 : "r"(a0), "r"(a1), "r"(a2), "r"(a3), "r"(b0), "r"(b1));
}
__device__ __forceinline__ void mma8b(float* d, u32 a0, u32 a1, u32 b0) {
    asm volatile("mma.sync.aligned.m16n8k8.row.col.f32.bf16.bf16.f32 "
                 "{%0,%1,%2,%3},{%4,%5},{%6},{%0,%1,%2,%3};"
                 : "+f"(d[0]), "+f"(d[1]), "+f"(d[2]), "+f"(d[3])
                 : "r"(a0), "r"(a1), "r"(b0));
}

// one k16 chunk: 2 m-halves x 4 gates x 3 compensation terms = 24 MMAs
__device__ __forceinline__ void chunk16(float (&acc)[2][4][4], const uint4* __restrict__ bb4, int rot,
                                        const u32* __restrict__ aH, const u32* __restrict__ aL,
                                        int laneK, int laneM) {
    uint4 B[4];
#pragma unroll
    for (int g = 0; g < 4; g++) B[g] = bb4[(g + rot) & 3];
#pragma unroll
    for (int h = 0; h < 2; h++) {
        const u32* pH = aH + laneK * APW + h * 16 + laneM;
        const u32* pL = aL + laneK * APW + h * 16 + laneM;
        u32 a0 = pH[0], a1 = pH[8], a2 = pH[4 * APW], a3 = pH[4 * APW + 8];
        u32 l0 = pL[0], l1 = pL[8], l2 = pL[4 * APW], l3 = pL[4 * APW + 8];
#pragma unroll
        for (int g = 0; g < 4; g++) {
            mma16(acc[h][g], a0, a1, a2, a3, B[g].x, B[g].y);
            mma16(acc[h][g], l0, l1, l2, l3, B[g].x, B[g].y);
            mma16(acc[h][g], a0, a1, a2, a3, B[g].z, B[g].w);
        }
    }
}

// x chunk (k=8)
__device__ __forceinline__ void chunk8(float (&acc)[2][4][4], const uint4* __restrict__ bb4, int rot,
                                       const u32* __restrict__ aH, const u32* __restrict__ aL,
                                       int laneK, int laneM) {
    uint4 B[4];
#pragma unroll
    for (int g = 0; g < 4; g++) B[g] = bb4[(g + rot) & 3];
#pragma unroll
    for (int h = 0; h < 2; h++) {
        const u32* pH = aH + laneK * APW + h * 16 + laneM;
        const u32* pL = aL + laneK * APW + h * 16 + laneM;
        u32 a0 = pH[0], a1 = pH[8];
        u32 l0 = pL[0], l1 = pL[8];
#pragma unroll
        for (int g = 0; g < 4; g++) {
            mma8b(acc[h][g], a0, a1, B[g].x);
            mma8b(acc[h][g], l0, l1, B[g].x);
            mma8b(acc[h][g], a0, a1, B[g].z);
        }
    }
}

__device__ __forceinline__ void acc_init(float (&acc)[2][4][4], const float* __restrict__ shB,
                                         int wid, int laneK) {
    int j = wid * 8 + 2 * laneK;
#pragma unroll
    for (int g = 0; g < 4; g++) {
        float bj  = shB[g * 128 + j];
        float bj1 = shB[g * 128 + j + 1];
#pragma unroll
        for (int h = 0; h < 2; h++) {
            acc[h][g][0] = bj; acc[h][g][1] = bj1;
            acc[h][g][2] = bj; acc[h][g][3] = bj1;
        }
    }
}

__device__ __forceinline__ void epilogue(float (&acc)[2][4][4], float* cst,
                                         u32* __restrict__ hHb, u32* __restrict__ hLb,
                                         int wid, int laneK, int laneM) {
    int jp = wid * 4 + laneK;
#pragma unroll
    for (int h = 0; h < 2; h++) {
#pragma unroll
        for (int rr = 0; rr < 2; rr++) {
            int m = h * 16 + laneM + rr * 8;
            float hv[2];
#pragma unroll
            for (int q = 0; q < 2; q++) {
                float zi = acc[h][0][rr * 2 + q], zf = acc[h][1][rr * 2 + q];
                float zg = acc[h][2][rr * 2 + q], zo = acc[h][3][rr * 2 + q];
                int ci = h * 4 + rr * 2 + q;
                float c = sigm(zf) * cst[ci] + sigm(zi) * tanhh(zg);
                cst[ci] = c;
                hv[q] = sigm(zo) * tanhh(c);
            }
            pack_hilo(hv[0], hv[1], &hHb[jp * APW + m], &hLb[jp * APW + m]);
        }
    }
}

// smem layout (u32 units)
#define SM_RING 0
#define SM_XH   (NSLOT * CHUNKU)            // 32768
#define SM_XL   (SM_XH + 4 * APW)
#define SM_H0H  (SM_XL + 4 * APW)
#define SM_H0L  (SM_H0H + 64 * APW)
#define SM_H1H  (SM_H0L + 64 * APW)
#define SM_H1L  (SM_H1H + 64 * APW)
#define SM_FLT  (SM_H1L + 64 * APW)
#define NFLT    (512 + 512 + 128 + 128 + MB * FCH + MB * OUTD)
#define SM_MB   (SM_FLT + NFLT)             // 8 mbarriers (2 u32 each)
#define SM_TOTB ((SM_MB + 16) * 4)

__global__ void __launch_bounds__(NTHR, 1) __cluster_dims__(2, 1, 1)
lstm_main(const float* __restrict__ x,
          const float* __restrict__ W2, const float* __restrict__ b2,
          const float* __restrict__ Wf, const float* __restrict__ bf,
          const float* __restrict__ b1fc,
          float* __restrict__ out, int steps)
{
    extern __shared__ u32 smu[];
    u32* ring = smu + SM_RING;
    u32* xH  = smu + SM_XH;
    u32* xL  = smu + SM_XL;
    u32* h0H = smu + SM_H0H;
    u32* h0L = smu + SM_H0L;
    u32* h1H = smu + SM_H1H;
    u32* h1L = smu + SM_H1L;
    float* shB0  = (float*)(smu + SM_FLT);
    float* shB1  = shB0 + 512;
    float* shBNs = shB1 + 512;
    float* shBNh = shBNs + 128;
    float* shO1  = shBNh + 128;
    float* shO2  = shO1 + MB * FCH;

    const int tid  = threadIdx.x;
    const int wid  = tid >> 5, lane = tid & 31;
    const int laneK = lane & 3, laneM = lane >> 2;
    const int rot  = (lane >> 1) & 3;
    const int b0 = blockIdx.x * MB;
    u32 rank; asm("mov.u32 %0, %%cluster_ctarank;" : "=r"(rank));

    const u32 ringb = smem_u32(ring);
    const u32 mbF   = smem_u32(smu + SM_MB);          // full[0..3]
    const u32 mbE   = mbF + 32;                       // empty[0..3]

    // init barriers, zero activation buffers, stage constants
    if (tid == 0) {
#pragma unroll
        for (int s = 0; s < 4; s++) {
            mbar_init(mbF + s * 8, 1);
            mbar_init(mbE + s * 8, 32);
        }
    }
    for (int i = tid; i < 8 * APW + 4 * 64 * APW; i += NTHR) xH[i] = 0;
    for (int i = tid; i < 512; i += NTHR) { shB0[i] = g_b0[i]; shB1[i] = g_b1[i]; }
    if (tid < H) { shBNs[tid] = g_bnsc[tid]; shBNh[tid] = g_bnsh[tid]; }

    float cst0[8], cst1[8];
#pragma unroll
    for (int i = 0; i < 8; i++) { cst0[i] = 0.f; cst1[i] = 0.f; }

    // stage x[0]
    if (tid < 128) {
        int kp = tid >> 5, m = tid & 31;
        const float* xp = x + ((size_t)(b0 + m) * TT + 0) * IN_D + 2 * kp;
        pack_hilo(xp[0], xp[1], &xH[kp * APW + m], &xL[kp * APW + m]);
    }
    __syncthreads();                 // barriers initialized, buffers ready

    // pre-post expects for initial chunks 0..2 (both CTAs)
    if (wid < 3 && lane == 0) mbar_expect(mbF + wid * 8, 32768u);
    CLUSTER_SYNC_();                 // all inits + expects visible cluster-wide
    if (rank == 0 && wid < 3 && lane == 0)
        bulk_mcast(ringb + (u32)wid * 32768u, g_Wperm + (size_t)wid * CHUNKU, mbF + wid * 8);

    const int total = TT + steps;
    const int tiles_total = total * NCHUNK;
    int cglob = 0;        // consume chunk counter
    int prp = 3;          // (cglob+3) % NCHUNK

#define PIPE_BEGIN() do { \
    int pc = cglob + 3; \
    if (pc < tiles_total && wid == (pc & 3) && lane == 0) { \
        mbar_expect(mbF + (pc & 3) * 8, 32768u); \
        if (rank == 0) { \
            if (pc >= 4) mbar_wait(mbE + (pc & 3) * 8, ((pc >> 2) - 1) & 1); \
            bulk_mcast(ringb + (u32)(pc & 3) * 32768u, g_Wperm + (size_t)prp * CHUNKU, \
                       mbF + (pc & 3) * 8); \
        } \
    } \
    mbar_wait(mbF + (cglob & 3) * 8, (cglob >> 2) & 1); \
} while (0)

#define PIPE_END() do { \
    if (lane == 0) mbar_arrive_rank0(mbE + (cglob & 3) * 8); \
    cglob++; prp = (prp == NCHUNK - 1) ? 0 : prp + 1; \
} while (0)

    for (int t = 0; t < total; t++) {
        bool dec = (t >= TT);
        float acc[2][4][4];

        // ---------------- layer 0: x chunk + 8 h0 chunks ----------------
        acc_init(acc, shB0, wid, laneK);
        PIPE_BEGIN();
        chunk8(acc, (const uint4*)(ring + (cglob & 3) * CHUNKU + wid * 512 + lane * 16), rot,
               xH, xL, laneK, laneM);
        PIPE_END();
#pragma unroll
        for (int r = 0; r < 8; r++) {
            PIPE_BEGIN();
            chunk16(acc, (const uint4*)(ring + (cglob & 3) * CHUNKU + wid * 512 + lane * 16), rot,
                    h0H + r * 8 * APW, h0L + r * 8 * APW, laneK, laneM);
            PIPE_END();
        }
        __syncthreads();                 // all warps done reading x, h0(old)
        epilogue(acc, cst0, h0H, h0L, wid, laneK, laneM);
        if (!dec && t + 1 < TT && tid < 128) {
            int kp = tid >> 5, m = tid & 31;
            const float* xp = x + ((size_t)(b0 + m) * TT + (t + 1)) * IN_D + 2 * kp;
            pack_hilo(xp[0], xp[1], &xH[kp * APW + m], &xL[kp * APW + m]);
        }
        __syncthreads();                 // h0(new) + x(next) published

        // ---------------- layer 1: 8 h0 chunks + 8 h1 chunks ----------------
        acc_init(acc, shB1, wid, laneK);
#pragma unroll
        for (int r = 0; r < 16; r++) {
            PIPE_BEGIN();
            const u32* aH = (r < 8) ? h0H + r * 8 * APW : h1H + (r - 8) * 8 * APW;
            const u32* aL = (r < 8) ? h0L + r * 8 * APW : h1L + (r - 8) * 8 * APW;
            chunk16(acc, (const uint4*)(ring + (cglob & 3) * CHUNKU + wid * 512 + lane * 16), rot,
                    aH, aL, laneK, laneM);
            PIPE_END();
        }
        __syncthreads();                 // all warps done reading h1(old)
        epilogue(acc, cst1, h1H, h1L, wid, laneK, laneM);

        if (dec) {
            int d = t - TT;
            __syncthreads();             // h1(new) visible
#pragma unroll
            for (int i = 0; i < (MB * FCH) / NTHR; i++) {
                int idx = tid + i * NTHR;
                int m = idx >> 6, n = idx & 63;
                float s = b1fc[n];
#pragma unroll 4
                for (int kp = 0; kp < 64; kp++) {
                    u32 wh = h1H[kp * APW + m], wl = h1L[kp * APW + m];
                    __nv_bfloat162 bh = *reinterpret_cast<__nv_bfloat162*>(&wh);
                    __nv_bfloat162 bl = *reinterpret_cast<__nv_bfloat162*>(&wl);
                    float ha = __bfloat162float(bh.x) + __bfloat162float(bl.x);
                    float hb = __bfloat162float(bh.y) + __bfloat162float(bl.y);
                    int k0 = 2 * kp;
                    float hn0 = ha * shBNs[k0] + shBNh[k0];
                    float hn1 = hb * shBNs[k0 + 1] + shBNh[k0 + 1];
                    s += hn0 * g_W1T[k0 * FCH + n] + hn1 * g_W1T[(k0 + 1) * FCH + n];
                }
                shO1[idx] = fmaxf(s, 0.f);
            }
            __syncthreads();
            if (tid < MB * OUTD) {
                int m = tid >> 2, o = tid & 3;
                float s = b2[o];
#pragma unroll 8
                for (int k = 0; k < FCH; k++) s += shO1[m * FCH + k] * W2[o * FCH + k];
                shO2[tid] = s;
                out[((size_t)(b0 + m) * steps + d) * OUTD + o] = s;
            }
            __syncthreads();
            if (tid < 128) {
                int kp = tid >> 5, m = tid & 31;
                float s0 = bf[2 * kp], s1 = bf[2 * kp + 1];
#pragma unroll
                for (int o = 0; o < OUTD; o++) {
                    float ov = shO2[m * OUTD + o];
                    s0 += ov * Wf[(2 * kp) * OUTD + o];
                    s1 += ov * Wf[(2 * kp + 1) * OUTD + o];
                }
                pack_hilo(s0, s1, &xH[kp * APW + m], &xL[kp * APW + m]);
            }
            __syncthreads();
        }
    }
#undef PIPE_BEGIN
#undef PIPE_END
    CLUSTER_SYNC_();                     // no CTA exits with peer traffic in flight
}

extern "C" void kernel_launch(void* const* d_in, const int* in_sizes, int n_in,
                              void* d_out, int out_size) {
    const float* x    = (const float*)d_in[0];
    const float* Wih0 = (const float*)d_in[1];
    const float* Whh0 = (const float*)d_in[2];
    const float* bih0 = (const float*)d_in[3];
    const float* bhh0 = (const float*)d_in[4];
    const float* Wih1 = (const float*)d_in[5];
    const float* Whh1 = (const float*)d_in[6];
    const float* bih1 = (const float*)d_in[7];
    const float* bhh1 = (const float*)d_in[8];
    const float* gam  = (const float*)d_in[9];
    const float* bet  = (const float*)d_in[10];
    const float* mean = (const float*)d_in[11];
    const float* var  = (const float*)d_in[12];
    const float* W1   = (const float*)d_in[13];
    const float* b1   = (const float*)d_in[14];
    const float* W2   = (const float*)d_in[15];
    const float* b2   = (const float*)d_in[16];
    const float* Wf   = (const float*)d_in[17];
    const float* bf   = (const float*)d_in[18];
    float* out = (float*)d_out;

    int B = in_sizes[0] / (TT * IN_D);
    int steps = out_size / (B * OUTD);

    cudaFuncSetAttribute(lstm_main, cudaFuncAttributeMaxDynamicSharedMemorySize, SM_TOTB);

    prep_kernel<<<256, 256>>>(Wih0, Whh0, bih0, bhh0, Wih1, Whh1, bih1, bhh1,
                              gam, bet, mean, var, W1);
    lstm_main<<<B / MB, NTHR, SM_TOTB>>>(x, W2, b2, Wf, bf, b1, out, steps);
}